// round 9
// baseline (speedup 1.0000x reference)
#include <cuda_runtime.h>
#include <cuda_bf16.h>
#include <cstddef>
#include <math.h>

#define BATCH 256
#define TT    2048
#define HID   128
#define G4    512           // 4*HID
#define MROWS (BATCH*TT)    // 524288

typedef unsigned long long ull;

// ---- scratch (static device arrays: sanctioned allocation-free path) ----
__device__ float g_out0[(size_t)MROWS * HID];   // layer0 hidden states [B*T, 128]
__device__ float g_xg1 [(size_t)MROWS * G4];    // layer1 input gates (+bias) [B*T, 512]

// ---------------- packed f32x2 helpers (sm_103a) ----------------
__device__ __forceinline__ ull pk2(float lo, float hi) {
    ull r; asm("mov.b64 %0, {%1, %2};" : "=l"(r) : "f"(lo), "f"(hi)); return r;
}
__device__ __forceinline__ float2 upk(ull v) {
    float2 r; asm("mov.b64 {%0, %1}, %2;" : "=f"(r.x), "=f"(r.y) : "l"(v)); return r;
}
__device__ __forceinline__ void ffma2(ull& d, ull a, ull b) {
    asm("fma.rn.f32x2 %0, %1, %2, %0;" : "+l"(d) : "l"(a), "l"(b));
}

// ---------------- fast activations ----------------
__device__ __forceinline__ float sigm_f(float v) {
    float e = __expf(-v);
    return __fdividef(1.0f, 1.0f + e);    // inf -> 0, 0 -> 1 : correct tails
}
__device__ __forceinline__ float tanh_f(float v) {
    float e = __expf(2.0f * v);           // 0 -> -1, inf -> +1 : correct tails
    return 1.0f - __fdividef(2.0f, 1.0f + e);
}

extern __shared__ __align__(16) unsigned char dynsm[];

// ---------------------------------------------------------------------------
// LSTM layer. 256 CTAs x 128 threads; CTA owns ONE batch row b = blockIdx.x.
// Thread j owns all 4 gate rows of hidden unit j: {j, j+128, j+256, j+384}.
//   i-row weights: smem, k-major ulonglong2 (conflict-free LDS.128)
//   f/g/o rows:    192 registers
// The c/h update is thread-local -> no gate exchange. h double-buffered in
// smem -> ONE __syncthreads per step. 2 CTAs/SM overlap barrier stalls.
// ---------------------------------------------------------------------------
#define SMEM_LSTM (32*128*16 /*Wi*/ + 2*HID*4 /*h dbl buf*/)

template<int LAYER>
__global__ void __launch_bounds__(128, 2)
lstm_kernel(const float* __restrict__ x,     // layer0: [B,T,1]
            const float* __restrict__ W_ih,  // layer0: [512,1]
            const float* __restrict__ W_hh,  // [512,128]
            const float* __restrict__ b_ih,
            const float* __restrict__ b_hh,
            const float* __restrict__ W_fc,  // layer1: [1,128]
            const float* __restrict__ b_fc,  // layer1: [1]
            float* __restrict__ out)
{
    ulonglong2* Wi   = (ulonglong2*)dynsm;            // [32][128] i-rows k-major
    float*      hbuf = (float*)(dynsm + 32*128*16);   // [2][128]

    const int j = threadIdx.x;       // hidden unit
    const int b = blockIdx.x;        // batch row
    const int ri = j, rf = j + 128, rg = j + 256, ro = j + 384;

    // ---- weight staging ----
    {
        const ulonglong2* wip = (const ulonglong2*)(W_hh + (size_t)ri * HID);
        #pragma unroll 4
        for (int q = 0; q < 32; q++)
            Wi[q * 128 + j] = wip[q];
    }
    ull wf[64], wg[64], wo[64];      // 32 ulonglong2 each, as ull pairs
    {
        const ull* p;
        p = (const ull*)(W_hh + (size_t)rf * HID);
        #pragma unroll
        for (int q = 0; q < 64; q++) wf[q] = p[q];
        p = (const ull*)(W_hh + (size_t)rg * HID);
        #pragma unroll
        for (int q = 0; q < 64; q++) wg[q] = p[q];
        p = (const ull*)(W_hh + (size_t)ro * HID);
        #pragma unroll
        for (int q = 0; q < 64; q++) wo[q] = p[q];
    }

    float wih_i = 0.f, wih_f = 0.f, wih_g = 0.f, wih_o = 0.f;
    float bs_i = 0.f, bs_f = 0.f, bs_g = 0.f, bs_o = 0.f;
    if (LAYER == 0) {
        wih_i = __ldg(&W_ih[ri]); wih_f = __ldg(&W_ih[rf]);
        wih_g = __ldg(&W_ih[rg]); wih_o = __ldg(&W_ih[ro]);
        bs_i = __ldg(&b_ih[ri]) + __ldg(&b_hh[ri]);
        bs_f = __ldg(&b_ih[rf]) + __ldg(&b_hh[rf]);
        bs_g = __ldg(&b_ih[rg]) + __ldg(&b_hh[rg]);
        bs_o = __ldg(&b_ih[ro]) + __ldg(&b_hh[ro]);
    }

    hbuf[j] = 0.f;
    hbuf[HID + j] = 0.f;
    float c = 0.f, hlast = 0.f;
    __syncthreads();

    for (int t = 0; t < TT; t++) {
        // --- input-gate contributions (loads issued early, used post-dot) ---
        float xi, xf, xg, xo;
        if (LAYER == 0) {
            float xv = __ldg(&x[(size_t)b * TT + t]);
            xi = fmaf(wih_i, xv, bs_i);
            xf = fmaf(wih_f, xv, bs_f);
            xg = fmaf(wih_g, xv, bs_g);
            xo = fmaf(wih_o, xv, bs_o);
        } else {
            const float* base = g_xg1 + ((size_t)b * TT + t) * G4;
            xi = __ldg(base + ri);
            xf = __ldg(base + rf);
            xg = __ldg(base + rg);
            xo = __ldg(base + ro);
        }

        // --- 4 dots of length 128 against h(t-1), K-packed f32x2 ---
        const ulonglong2* hp = (const ulonglong2*)(hbuf + (t & 1) * HID);

        ull ai_a = pk2(xi, 0.f), ai_b = pk2(0.f, 0.f);
        ull af_a = pk2(xf, 0.f), af_b = pk2(0.f, 0.f);
        ull ag_a = pk2(xg, 0.f), ag_b = pk2(0.f, 0.f);
        ull ao_a = pk2(xo, 0.f), ao_b = pk2(0.f, 0.f);

        #pragma unroll
        for (int q = 0; q < 32; q++) {
            ulonglong2 hv = hp[q];                 // broadcast (4 floats)
            ulonglong2 wi = Wi[q * 128 + j];       // i-row weights (smem)
            ffma2(ai_a, wi.x,        hv.x); ffma2(ai_b, wi.y,        hv.y);
            ffma2(af_a, wf[2*q],     hv.x); ffma2(af_b, wf[2*q + 1], hv.y);
            ffma2(ag_a, wg[2*q],     hv.x); ffma2(ag_b, wg[2*q + 1], hv.y);
            ffma2(ao_a, wo[2*q],     hv.x); ffma2(ao_b, wo[2*q + 1], hv.y);
        }

        float2 u;
        u = upk(ai_a); float ai = u.x + u.y; u = upk(ai_b); ai += u.x + u.y;
        u = upk(af_a); float af = u.x + u.y; u = upk(af_b); af += u.x + u.y;
        u = upk(ag_a); float ag = u.x + u.y; u = upk(ag_b); ag += u.x + u.y;
        u = upk(ao_a); float ao = u.x + u.y; u = upk(ao_b); ao += u.x + u.y;

        // --- thread-local gate + cell/hidden update (no exchange) ---
        float iv = sigm_f(ai);
        float fv = sigm_f(af);
        float gv = tanh_f(ag);
        float ov = sigm_f(ao);
        c = fmaf(fv, c, iv * gv);
        float h = ov * tanh_f(c);
        hlast = h;

        hbuf[((t + 1) & 1) * HID + j] = h;
        if (LAYER == 0)
            g_out0[((size_t)b * TT + t) * HID + j] = h;

        __syncthreads();   // h(t) visible to all before next step's dot
    }

    // --- finals. out: y[256] | h_n[2][256][128] | c_n[2][256][128] ---
    out[256 + ((size_t)LAYER * BATCH + b) * HID + j] = hlast;
    out[256 + (size_t)2 * BATCH * HID
            + ((size_t)LAYER * BATCH + b) * HID + j] = c;

    // --- FC head (layer 1): y[b] = h_final . W_fc + b_fc ---
    if (LAYER == 1 && j < 32) {
        // final h lives in hbuf[(TT)&1 == 0]
        float s = 0.f;
        #pragma unroll
        for (int q = j; q < HID; q += 32)
            s = fmaf(hbuf[q], __ldg(&W_fc[q]), s);
        #pragma unroll
        for (int off = 16; off > 0; off >>= 1)
            s += __shfl_down_sync(0xffffffffu, s, off);
        if (j == 0)
            out[b] = s + __ldg(&b_fc[0]);
    }
}

// ---------------------------------------------------------------------------
// GEMM: g_xg1[M,512] = g_out0[M,128] @ W_ih1^T + (b_ih1 + b_hh1)
// Tile 256(M) x 64(N), 512 threads, single K=128 pass.
// At [128k][264m] transposed (m-pairs load as packed f32x2),
// Bs2 [128k][64n] pre-duplicated (w,w) ull -> per k-iter: 4 LDS.128 + 16 FFMA2.
// 197KB smem, 1 CTA/SM, 16 warps. Grid x = n-tile fastest (A-tile L2 reuse).
// ---------------------------------------------------------------------------
#define AT_LD 264
#define SMEM_GEMM (128*AT_LD*4 /*At*/ + 128*64*8 /*Bs2*/ + 64*4 /*bias*/)

__global__ void __launch_bounds__(512, 1)
gemm_xg1_kernel(const float* __restrict__ W,     // W_ih_l1 [512,128]
                const float* __restrict__ b_ih,
                const float* __restrict__ b_hh)
{
    float* At     = (float*)dynsm;                        // [128][264]
    ull*   Bs2    = (ull*)(dynsm + 128*AT_LD*4);          // [128][64]
    float* bias_s = (float*)(dynsm + 128*AT_LD*4 + 128*64*8);

    const int tid = threadIdx.x;
    const int n0  = blockIdx.x * 64;
    const int m0  = blockIdx.y * 256;

    if (tid < 64)
        bias_s[tid] = __ldg(&b_ih[n0 + tid]) + __ldg(&b_hh[n0 + tid]);

    // load A: 256m x 128k -> transposed [k][m]
    {
        const int ar = tid >> 1;              // m row 0..255
        const int ak = (tid & 1) * 64;        // k half
        const float4* ap = (const float4*)(g_out0 + (size_t)(m0 + ar) * HID + ak);
        #pragma unroll
        for (int q = 0; q < 16; q++) {
            float4 v = ap[q];
            At[(ak + q*4 + 0) * AT_LD + ar] = v.x;
            At[(ak + q*4 + 1) * AT_LD + ar] = v.y;
            At[(ak + q*4 + 2) * AT_LD + ar] = v.z;
            At[(ak + q*4 + 3) * AT_LD + ar] = v.w;
        }
    }
    // load B: 64n x 128k -> [k][n], duplicated (w,w)
    {
        const int bn = tid & 63;              // n row
        const int bk = (tid >> 6) * 16;       // k segment of 16
        const float4* bp = (const float4*)(W + (size_t)(n0 + bn) * HID + bk);
        #pragma unroll
        for (int q = 0; q < 4; q++) {
            float4 v = bp[q];
            Bs2[(bk + q*4 + 0) * 64 + bn] = pk2(v.x, v.x);
            Bs2[(bk + q*4 + 1) * 64 + bn] = pk2(v.y, v.y);
            Bs2[(bk + q*4 + 2) * 64 + bn] = pk2(v.z, v.z);
            Bs2[(bk + q*4 + 3) * 64 + bn] = pk2(v.w, v.w);
        }
    }
    __syncthreads();

    const int tx = tid & 15;   // n cols tx*4 .. +3
    const int ty = tid >> 4;   // m rows ty*8 .. +7 (4 packed pairs)

    ull acc[4][4];
    #pragma unroll
    for (int i = 0; i < 4; i++)
        #pragma unroll
        for (int jj = 0; jj < 4; jj++) acc[i][jj] = pk2(0.f, 0.f);

    #pragma unroll 4
    for (int k = 0; k < 128; k++) {
        ulonglong2 a01 = *(const ulonglong2*)&At[k * AT_LD + ty * 8];
        ulonglong2 a23 = *(const ulonglong2*)&At[k * AT_LD + ty * 8 + 4];
        ulonglong2 b01 = *(const ulonglong2*)&Bs2[k * 64 + tx * 4];
        ulonglong2 b23 = *(const ulonglong2*)&Bs2[k * 64 + tx * 4 + 2];
        ffma2(acc[0][0], a01.x, b01.x); ffma2(acc[0][1], a01.x, b01.y);
        ffma2(acc[0][2], a01.x, b23.x); ffma2(acc[0][3], a01.x, b23.y);
        ffma2(acc[1][0], a01.y, b01.x); ffma2(acc[1][1], a01.y, b01.y);
        ffma2(acc[1][2], a01.y, b23.x); ffma2(acc[1][3], a01.y, b23.y);
        ffma2(acc[2][0], a23.x, b01.x); ffma2(acc[2][1], a23.x, b01.y);
        ffma2(acc[2][2], a23.x, b23.x); ffma2(acc[2][3], a23.x, b23.y);
        ffma2(acc[3][0], a23.y, b01.x); ffma2(acc[3][1], a23.y, b01.y);
        ffma2(acc[3][2], a23.y, b23.x); ffma2(acc[3][3], a23.y, b23.y);
    }

    // store C (+bias)
    float bx = bias_s[tx*4 + 0], by = bias_s[tx*4 + 1];
    float bz = bias_s[tx*4 + 2], bw = bias_s[tx*4 + 3];
    #pragma unroll
    for (int mp = 0; mp < 4; mp++) {
        float2 c0 = upk(acc[mp][0]), c1 = upk(acc[mp][1]);
        float2 c2 = upk(acc[mp][2]), c3 = upk(acc[mp][3]);
        size_t mA = (size_t)(m0 + ty * 8 + 2 * mp);
        float4 vA = make_float4(c0.x + bx, c1.x + by, c2.x + bz, c3.x + bw);
        float4 vB = make_float4(c0.y + bx, c1.y + by, c2.y + bz, c3.y + bw);
        *(float4*)&g_xg1[mA * G4 + n0 + tx * 4]       = vA;
        *(float4*)&g_xg1[(mA + 1) * G4 + n0 + tx * 4] = vB;
    }
}

// ---------------------------------------------------------------------------
// Launch
// ---------------------------------------------------------------------------
extern "C" void kernel_launch(void* const* d_in, const int* in_sizes, int n_in,
                              void* d_out, int out_size)
{
    const float* x      = (const float*)d_in[0];   // [256,2048,1]
    const float* W_ih0  = (const float*)d_in[1];   // [512,1]
    const float* W_hh0  = (const float*)d_in[2];   // [512,128]
    const float* b_ih0  = (const float*)d_in[3];
    const float* b_hh0  = (const float*)d_in[4];
    const float* W_ih1  = (const float*)d_in[5];   // [512,128]
    const float* W_hh1  = (const float*)d_in[6];   // [512,128]
    const float* b_ih1  = (const float*)d_in[7];
    const float* b_hh1  = (const float*)d_in[8];
    const float* W_fc   = (const float*)d_in[9];   // [1,128]
    const float* b_fc   = (const float*)d_in[10];  // [1]
    float* out = (float*)d_out;

    cudaFuncSetAttribute(lstm_kernel<0>, cudaFuncAttributeMaxDynamicSharedMemorySize, SMEM_LSTM);
    cudaFuncSetAttribute(lstm_kernel<1>, cudaFuncAttributeMaxDynamicSharedMemorySize, SMEM_LSTM);
    cudaFuncSetAttribute(gemm_xg1_kernel, cudaFuncAttributeMaxDynamicSharedMemorySize, SMEM_GEMM);

    // Layer 0 recurrence (writes g_out0, h_n[0], c_n[0])
    lstm_kernel<0><<<BATCH, 128, SMEM_LSTM>>>(
        x, W_ih0, W_hh0, b_ih0, b_hh0, nullptr, nullptr, out);

    // Layer 1 input gates: g_xg1 = g_out0 @ W_ih1^T + bias
    {
        dim3 grid(G4 / 64, MROWS / 256);   // x = n-tile fastest (A-tile L2 reuse)
        gemm_xg1_kernel<<<grid, 512, SMEM_GEMM>>>(W_ih1, b_ih1, b_hh1);
    }

    // Layer 1 recurrence (reads g_xg1; writes h_n[1], c_n[1], y)
    lstm_kernel<1><<<BATCH, 128, SMEM_LSTM>>>(
        nullptr, nullptr, W_hh1, b_ih1, b_hh1, W_fc, b_fc, out);
}

// round 10
// speedup vs baseline: 2.7055x; 2.7055x over previous
#include <cuda_runtime.h>
#include <cuda_bf16.h>
#include <cstddef>
#include <math.h>

#define BATCH 256
#define TT    2048
#define HID   128
#define G4    512           // 4*HID
#define MROWS (BATCH*TT)    // 524288

typedef unsigned long long ull;

// ---- scratch (static device arrays: sanctioned allocation-free path) ----
__device__ float g_out0[(size_t)MROWS * HID];   // layer0 hidden states [B*T, 128]
__device__ float g_xg1 [(size_t)MROWS * G4];    // layer1 input gates (+bias) [B*T, 512]

// ---------------- packed f32x2 helpers (sm_103a) ----------------
__device__ __forceinline__ ull pk2(float lo, float hi) {
    ull r; asm("mov.b64 %0, {%1, %2};" : "=l"(r) : "f"(lo), "f"(hi)); return r;
}
__device__ __forceinline__ float2 upk(ull v) {
    float2 r; asm("mov.b64 {%0, %1}, %2;" : "=f"(r.x), "=f"(r.y) : "l"(v)); return r;
}
__device__ __forceinline__ void ffma2(ull& d, ull a, ull b) {
    asm("fma.rn.f32x2 %0, %1, %2, %0;" : "+l"(d) : "l"(a), "l"(b));
}

// ---------------- fast activations ----------------
__device__ __forceinline__ float sigm_f(float v) {
    float e = __expf(-v);
    return __fdividef(1.0f, 1.0f + e);    // inf -> 0, 0 -> 1 : correct tails
}
__device__ __forceinline__ float tanh_f(float v) {
    float e = __expf(2.0f * v);           // 0 -> -1, inf -> +1 : correct tails
    return 1.0f - __fdividef(2.0f, 1.0f + e);
}

extern __shared__ __align__(16) unsigned char dynsm[];

// ---------------------------------------------------------------------------
// LSTM layer (R8 structure + pipelined xg + p-trick exchange).
// 128 CTAs x 256 threads; CTA owns batch rows 2*bx, 2*bx+1.
// Thread tid owns gate rows r0 = tid (SMEM, k-major ulonglong2) and
// r1 = tid+256 (128 registers) for BOTH batch rows.
//   tid <  128 : r0 = i_j, r1 = g_j  -> computes p = sigm(i)*tanh(g), writes p
//   tid >= 128 : r0 = f_j, r1 = o_j  -> owns c_j; after sync reads p, updates
//                c/h thread-locally, publishes h. 2 syncs/step.
// xg(t+1) is prefetched during step t's dot; accumulators seed with 0 and xg
// is added post-dot, so global-load latency is fully hidden.
// ---------------------------------------------------------------------------
#define SMEM_LSTM (32*256*16 /*Wsm*/ + 2*HID*4 /*h*/ + 2*HID*4 /*p*/)

template<int LAYER>
__global__ void __launch_bounds__(256, 1)
lstm_kernel(const float* __restrict__ x,     // layer0: [B,T,1]
            const float* __restrict__ W_ih,  // layer0: [512,1]
            const float* __restrict__ W_hh,  // [512,128]
            const float* __restrict__ b_ih,
            const float* __restrict__ b_hh,
            const float* __restrict__ W_fc,  // layer1: [1,128]
            const float* __restrict__ b_fc,  // layer1: [1]
            float* __restrict__ out)
{
    ulonglong2* Wsm  = (ulonglong2*)dynsm;              // [32][256] r0 rows, k-major
    float*      h_sm = (float*)(dynsm + 32*256*16);     // [2][128]
    float*      p_sm = h_sm + 2 * HID;                  // [128][2]

    const int tid = threadIdx.x;
    const int b0  = blockIdx.x * 2;
    const int r0  = tid;
    const int r1  = 256 + tid;

    // ---- weight staging: r0 -> smem (k-major), r1 -> registers ----
    {
        const ulonglong2* w0p = (const ulonglong2*)(W_hh + (size_t)r0 * HID);
        #pragma unroll 4
        for (int q = 0; q < 32; q++)
            Wsm[q * 256 + tid] = w0p[q];
    }
    ulonglong2 wreg[32];
    {
        const ulonglong2* w1p = (const ulonglong2*)(W_hh + (size_t)r1 * HID);
        #pragma unroll
        for (int q = 0; q < 32; q++)
            wreg[q] = w1p[q];
    }

    float wih0 = 0.f, wih1 = 0.f, bias0 = 0.f, bias1 = 0.f;
    if (LAYER == 0) {
        wih0  = __ldg(&W_ih[r0]);
        wih1  = __ldg(&W_ih[r1]);
        bias0 = __ldg(&b_ih[r0]) + __ldg(&b_hh[r0]);
        bias1 = __ldg(&b_ih[r1]) + __ldg(&b_hh[r1]);
    }

    h_sm[tid] = 0.f;            // covers [0, 2*HID)
    float c0 = 0.f, c1 = 0.f;   // cell states (upper threads own unit j=tid-128)
    float hl0 = 0.f, hl1 = 0.f; // final h (upper threads)
    __syncthreads();

    const ulonglong2* hp0 = (const ulonglong2*)h_sm;          // 32 chunks
    const ulonglong2* hp1 = (const ulonglong2*)(h_sm + HID);

    // ---- xg prefetch pipeline: load xg(0) ----
    float xg00, xg01, xg10, xg11;
    if (LAYER == 0) {
        float xv0 = __ldg(&x[(size_t)b0 * TT]);
        float xv1 = __ldg(&x[(size_t)(b0 + 1) * TT]);
        xg00 = fmaf(wih0, xv0, bias0);
        xg01 = fmaf(wih0, xv1, bias0);
        xg10 = fmaf(wih1, xv0, bias1);
        xg11 = fmaf(wih1, xv1, bias1);
    } else {
        const float* p0 = g_xg1 + (size_t)b0 * TT * G4;
        const float* p1 = g_xg1 + (size_t)(b0 + 1) * TT * G4;
        xg00 = __ldg(p0 + r0);
        xg01 = __ldg(p1 + r0);
        xg10 = __ldg(p0 + r1);
        xg11 = __ldg(p1 + r1);
    }

    for (int t = 0; t < TT; t++) {
        // current-step xg (already resident)
        const float cx00 = xg00, cx01 = xg01, cx10 = xg10, cx11 = xg11;

        // --- prefetch xg(t+1): LDGs issued now, consumed next iteration ---
        {
            const int tn = (t + 1 < TT) ? t + 1 : t;
            if (LAYER == 0) {
                float xv0 = __ldg(&x[(size_t)b0 * TT + tn]);
                float xv1 = __ldg(&x[(size_t)(b0 + 1) * TT + tn]);
                xg00 = fmaf(wih0, xv0, bias0);
                xg01 = fmaf(wih0, xv1, bias0);
                xg10 = fmaf(wih1, xv0, bias1);
                xg11 = fmaf(wih1, xv1, bias1);
            } else {
                const float* p0 = g_xg1 + ((size_t)b0 * TT + tn) * G4;
                const float* p1 = g_xg1 + ((size_t)(b0 + 1) * TT + tn) * G4;
                xg00 = __ldg(p0 + r0);
                xg01 = __ldg(p1 + r0);
                xg10 = __ldg(p0 + r1);
                xg11 = __ldg(p1 + r1);
            }
        }

        // --- 4 dots of length 128, K-packed f32x2, 2 chains each ---
        ull a00a = pk2(0.f, 0.f), a00b = pk2(0.f, 0.f);   // (r0, b0)
        ull a01a = pk2(0.f, 0.f), a01b = pk2(0.f, 0.f);   // (r0, b1)
        ull a10a = pk2(0.f, 0.f), a10b = pk2(0.f, 0.f);   // (r1, b0)
        ull a11a = pk2(0.f, 0.f), a11b = pk2(0.f, 0.f);   // (r1, b1)

        #pragma unroll
        for (int q = 0; q < 32; q++) {
            ulonglong2 wA = Wsm[q * 256 + tid];   // r0 weights (smem)
            ulonglong2 h0 = hp0[q];               // broadcast
            ulonglong2 h1 = hp1[q];               // broadcast
            ulonglong2 wB = wreg[q];              // r1 weights (regs)
            ffma2(a00a, wA.x, h0.x); ffma2(a00b, wA.y, h0.y);
            ffma2(a01a, wA.x, h1.x); ffma2(a01b, wA.y, h1.y);
            ffma2(a10a, wB.x, h0.x); ffma2(a10b, wB.y, h0.y);
            ffma2(a11a, wB.x, h1.x); ffma2(a11b, wB.y, h1.y);
        }

        float2 u;
        u = upk(a00a); float s00 = u.x + u.y; u = upk(a00b); s00 += u.x + u.y + cx00;
        u = upk(a01a); float s01 = u.x + u.y; u = upk(a01b); s01 += u.x + u.y + cx01;
        u = upk(a10a); float s10 = u.x + u.y; u = upk(a10b); s10 += u.x + u.y + cx10;
        u = upk(a11a); float s11 = u.x + u.y; u = upk(a11b); s11 += u.x + u.y + cx11;

        // --- lower half: p = sigm(i)*tanh(g); upper half: f,o activations ---
        float fv0, fv1, ov0, ov1;
        if (tid < 128) {
            float pb0 = sigm_f(s00) * tanh_f(s10);
            float pb1 = sigm_f(s01) * tanh_f(s11);
            *(float2*)&p_sm[2 * tid] = make_float2(pb0, pb1);
        } else {
            fv0 = sigm_f(s00); fv1 = sigm_f(s01);
            ov0 = sigm_f(s10); ov1 = sigm_f(s11);
        }
        __syncthreads();

        // --- upper half: thread-local cell/hidden update, publish h ---
        if (tid >= 128) {
            const int j = tid - 128;
            float2 p = *(const float2*)&p_sm[2 * j];
            c0 = fmaf(fv0, c0, p.x);
            c1 = fmaf(fv1, c1, p.y);
            float h0 = ov0 * tanh_f(c0);
            float h1 = ov1 * tanh_f(c1);
            hl0 = h0; hl1 = h1;
            h_sm[j]       = h0;
            h_sm[HID + j] = h1;
            if (LAYER == 0) {
                g_out0[((size_t)b0 * TT + t) * HID + j]       = h0;
                g_out0[((size_t)(b0 + 1) * TT + t) * HID + j] = h1;
            }
        }
        __syncthreads();
    }

    // --- finals. out: y[256] | h_n[2][256][128] | c_n[2][256][128] ---
    if (tid >= 128) {
        const int j = tid - 128;
        out[256 + ((size_t)LAYER * BATCH + b0) * HID + j]     = hl0;
        out[256 + ((size_t)LAYER * BATCH + b0 + 1) * HID + j] = hl1;
        out[256 + (size_t)2 * BATCH * HID
                + ((size_t)LAYER * BATCH + b0) * HID + j]     = c0;
        out[256 + (size_t)2 * BATCH * HID
                + ((size_t)LAYER * BATCH + b0 + 1) * HID + j] = c1;
    }

    // --- FC head (layer 1): y[b] = h_final . W_fc + b_fc ---
    if (LAYER == 1 && tid < 64) {
        int w = tid >> 5;          // batch slot 0/1
        int l = tid & 31;
        float s = 0.f;
        #pragma unroll
        for (int q = l; q < HID; q += 32)
            s = fmaf(h_sm[w * HID + q], __ldg(&W_fc[q]), s);
        #pragma unroll
        for (int off = 16; off > 0; off >>= 1)
            s += __shfl_down_sync(0xffffffffu, s, off);
        if (l == 0)
            out[b0 + w] = s + __ldg(&b_fc[0]);
    }
}

// ---------------------------------------------------------------------------
// GEMM: g_xg1[M,512] = g_out0[M,128] @ W_ih1^T + (b_ih1 + b_hh1)
// Tile 256(M) x 64(N), 512 threads, single K=128 pass.
// At [128k][264m] transposed (m-pairs load as packed f32x2),
// Bs2 [128k][64n] pre-duplicated (w,w) ull -> per k-iter: 4 LDS.128 + 16 FFMA2.
// (correctness-verified in R9 run)
// ---------------------------------------------------------------------------
#define AT_LD 264
#define SMEM_GEMM (128*AT_LD*4 /*At*/ + 128*64*8 /*Bs2*/ + 64*4 /*bias*/)

__global__ void __launch_bounds__(512, 1)
gemm_xg1_kernel(const float* __restrict__ W,     // W_ih_l1 [512,128]
                const float* __restrict__ b_ih,
                const float* __restrict__ b_hh)
{
    float* At     = (float*)dynsm;                        // [128][264]
    ull*   Bs2    = (ull*)(dynsm + 128*AT_LD*4);          // [128][64]
    float* bias_s = (float*)(dynsm + 128*AT_LD*4 + 128*64*8);

    const int tid = threadIdx.x;
    const int n0  = blockIdx.x * 64;
    const int m0  = blockIdx.y * 256;

    if (tid < 64)
        bias_s[tid] = __ldg(&b_ih[n0 + tid]) + __ldg(&b_hh[n0 + tid]);

    // load A: 256m x 128k -> transposed [k][m]
    {
        const int ar = tid >> 1;              // m row 0..255
        const int ak = (tid & 1) * 64;        // k half
        const float4* ap = (const float4*)(g_out0 + (size_t)(m0 + ar) * HID + ak);
        #pragma unroll
        for (int q = 0; q < 16; q++) {
            float4 v = ap[q];
            At[(ak + q*4 + 0) * AT_LD + ar] = v.x;
            At[(ak + q*4 + 1) * AT_LD + ar] = v.y;
            At[(ak + q*4 + 2) * AT_LD + ar] = v.z;
            At[(ak + q*4 + 3) * AT_LD + ar] = v.w;
        }
    }
    // load B: 64n x 128k -> [k][n], duplicated (w,w)
    {
        const int bn = tid & 63;              // n row
        const int bk = (tid >> 6) * 16;       // k segment of 16
        const float4* bp = (const float4*)(W + (size_t)(n0 + bn) * HID + bk);
        #pragma unroll
        for (int q = 0; q < 4; q++) {
            float4 v = bp[q];
            Bs2[(bk + q*4 + 0) * 64 + bn] = pk2(v.x, v.x);
            Bs2[(bk + q*4 + 1) * 64 + bn] = pk2(v.y, v.y);
            Bs2[(bk + q*4 + 2) * 64 + bn] = pk2(v.z, v.z);
            Bs2[(bk + q*4 + 3) * 64 + bn] = pk2(v.w, v.w);
        }
    }
    __syncthreads();

    const int tx = tid & 15;   // n cols tx*4 .. +3
    const int ty = tid >> 4;   // m rows ty*8 .. +7 (4 packed pairs)

    ull acc[4][4];
    #pragma unroll
    for (int i = 0; i < 4; i++)
        #pragma unroll
        for (int jj = 0; jj < 4; jj++) acc[i][jj] = pk2(0.f, 0.f);

    #pragma unroll 4
    for (int k = 0; k < 128; k++) {
        ulonglong2 a01 = *(const ulonglong2*)&At[k * AT_LD + ty * 8];
        ulonglong2 a23 = *(const ulonglong2*)&At[k * AT_LD + ty * 8 + 4];
        ulonglong2 b01 = *(const ulonglong2*)&Bs2[k * 64 + tx * 4];
        ulonglong2 b23 = *(const ulonglong2*)&Bs2[k * 64 + tx * 4 + 2];
        ffma2(acc[0][0], a01.x, b01.x); ffma2(acc[0][1], a01.x, b01.y);
        ffma2(acc[0][2], a01.x, b23.x); ffma2(acc[0][3], a01.x, b23.y);
        ffma2(acc[1][0], a01.y, b01.x); ffma2(acc[1][1], a01.y, b01.y);
        ffma2(acc[1][2], a01.y, b23.x); ffma2(acc[1][3], a01.y, b23.y);
        ffma2(acc[2][0], a23.x, b01.x); ffma2(acc[2][1], a23.x, b01.y);
        ffma2(acc[2][2], a23.x, b23.x); ffma2(acc[2][3], a23.x, b23.y);
        ffma2(acc[3][0], a23.y, b01.x); ffma2(acc[3][1], a23.y, b01.y);
        ffma2(acc[3][2], a23.y, b23.x); ffma2(acc[3][3], a23.y, b23.y);
    }

    // store C (+bias)
    float bx = bias_s[tx*4 + 0], by = bias_s[tx*4 + 1];
    float bz = bias_s[tx*4 + 2], bw = bias_s[tx*4 + 3];
    #pragma unroll
    for (int mp = 0; mp < 4; mp++) {
        float2 cc0 = upk(acc[mp][0]), cc1 = upk(acc[mp][1]);
        float2 cc2 = upk(acc[mp][2]), cc3 = upk(acc[mp][3]);
        size_t mA = (size_t)(m0 + ty * 8 + 2 * mp);
        float4 vA = make_float4(cc0.x + bx, cc1.x + by, cc2.x + bz, cc3.x + bw);
        float4 vB = make_float4(cc0.y + bx, cc1.y + by, cc2.y + bz, cc3.y + bw);
        *(float4*)&g_xg1[mA * G4 + n0 + tx * 4]       = vA;
        *(float4*)&g_xg1[(mA + 1) * G4 + n0 + tx * 4] = vB;
    }
}

// ---------------------------------------------------------------------------
// Launch
// ---------------------------------------------------------------------------
extern "C" void kernel_launch(void* const* d_in, const int* in_sizes, int n_in,
                              void* d_out, int out_size)
{
    const float* x      = (const float*)d_in[0];   // [256,2048,1]
    const float* W_ih0  = (const float*)d_in[1];   // [512,1]
    const float* W_hh0  = (const float*)d_in[2];   // [512,128]
    const float* b_ih0  = (const float*)d_in[3];
    const float* b_hh0  = (const float*)d_in[4];
    const float* W_ih1  = (const float*)d_in[5];   // [512,128]
    const float* W_hh1  = (const float*)d_in[6];   // [512,128]
    const float* b_ih1  = (const float*)d_in[7];
    const float* b_hh1  = (const float*)d_in[8];
    const float* W_fc   = (const float*)d_in[9];   // [1,128]
    const float* b_fc   = (const float*)d_in[10];  // [1]
    float* out = (float*)d_out;

    cudaFuncSetAttribute(lstm_kernel<0>, cudaFuncAttributeMaxDynamicSharedMemorySize, SMEM_LSTM);
    cudaFuncSetAttribute(lstm_kernel<1>, cudaFuncAttributeMaxDynamicSharedMemorySize, SMEM_LSTM);
    cudaFuncSetAttribute(gemm_xg1_kernel, cudaFuncAttributeMaxDynamicSharedMemorySize, SMEM_GEMM);

    // Layer 0 recurrence (writes g_out0, h_n[0], c_n[0])
    lstm_kernel<0><<<BATCH/2, 256, SMEM_LSTM>>>(
        x, W_ih0, W_hh0, b_ih0, b_hh0, nullptr, nullptr, out);

    // Layer 1 input gates: g_xg1 = g_out0 @ W_ih1^T + bias
    {
        dim3 grid(G4 / 64, MROWS / 256);   // x = n-tile fastest (A-tile L2 reuse)
        gemm_xg1_kernel<<<grid, 512, SMEM_GEMM>>>(W_ih1, b_ih1, b_hh1);
    }

    // Layer 1 recurrence (reads g_xg1; writes h_n[1], c_n[1], y)
    lstm_kernel<1><<<BATCH/2, 256, SMEM_LSTM>>>(
        nullptr, nullptr, W_hh1, b_ih1, b_hh1, W_fc, b_fc, out);
}

// round 11
// speedup vs baseline: 4.7951x; 1.7723x over previous
#include <cuda_runtime.h>
#include <cuda_bf16.h>
#include <cstddef>
#include <stdint.h>
#include <math.h>

#define BATCH 256
#define TT    2048
#define HID   128
#define G4    512           // 4*HID
#define MROWS (BATCH*TT)    // 524288

typedef unsigned long long ull;

// ---- scratch (static device arrays: sanctioned allocation-free path) ----
__device__ float g_out0[(size_t)MROWS * HID];   // layer0 hidden states [B*T, 128]
__device__ float g_xg1 [(size_t)MROWS * G4];    // layer1 input gates (+bias) [B*T, 512]

// ---------------- packed f32x2 helpers (sm_103a) ----------------
__device__ __forceinline__ ull pk2(float lo, float hi) {
    ull r; asm("mov.b64 %0, {%1, %2};" : "=l"(r) : "f"(lo), "f"(hi)); return r;
}
__device__ __forceinline__ float2 upk(ull v) {
    float2 r; asm("mov.b64 {%0, %1}, %2;" : "=f"(r.x), "=f"(r.y) : "l"(v)); return r;
}
__device__ __forceinline__ void ffma2(ull& d, ull a, ull b) {
    asm("fma.rn.f32x2 %0, %1, %2, %0;" : "+l"(d) : "l"(a), "l"(b));
}

// ---------------- fast activations ----------------
__device__ __forceinline__ float sigm_f(float v) {
    float e = __expf(-v);
    return __fdividef(1.0f, 1.0f + e);    // inf -> 0, 0 -> 1 : correct tails
}
__device__ __forceinline__ float tanh_f(float v) {
    float e = __expf(2.0f * v);           // 0 -> -1, inf -> +1 : correct tails
    return 1.0f - __fdividef(2.0f, 1.0f + e);
}

// ---------------- tf32 helpers ----------------
__device__ __forceinline__ uint32_t cvt_tf32(float f) {
    uint32_t r; asm("cvt.rna.tf32.f32 %0, %1;" : "=r"(r) : "f"(f)); return r;
}
__device__ __forceinline__ void mma_tf32(float* c, uint4 a, uint32_t b0, uint32_t b1) {
    asm volatile("mma.sync.aligned.m16n8k8.row.col.f32.tf32.tf32.f32 "
        "{%0,%1,%2,%3}, {%4,%5,%6,%7}, {%8,%9}, {%0,%1,%2,%3};"
        : "+f"(c[0]), "+f"(c[1]), "+f"(c[2]), "+f"(c[3])
        : "r"(a.x), "r"(a.y), "r"(a.z), "r"(a.w), "r"(b0), "r"(b1));
}

extern __shared__ __align__(16) unsigned char dynsm[];

// ---------------------------------------------------------------------------
// LSTM layer — EXACT R8 structure (measured 2717us/layer).
// 128 CTAs x 256 threads; CTA owns batch rows 2*bx, 2*bx+1.
// Thread owns gate rows r0 = tid (weights in SMEM, k-major ulonglong2,
// conflict-free LDS.128) and r1 = tid+256 (weights fully in 128 registers),
// for BOTH batch rows -> 4 dots/thread/step. Two __syncthreads per step.
// ---------------------------------------------------------------------------
#define SMEM_LSTM (32*256*16 /*Wsm*/ + 2*HID*4 /*h*/ + 2*G4*4 /*gates*/)

template<int LAYER>
__global__ void __launch_bounds__(256, 1)
lstm_kernel(const float* __restrict__ x,     // layer0: [B,T,1]
            const float* __restrict__ W_ih,  // layer0: [512,1]
            const float* __restrict__ W_hh,  // [512,128]
            const float* __restrict__ b_ih,
            const float* __restrict__ b_hh,
            const float* __restrict__ W_fc,  // layer1: [1,128]
            const float* __restrict__ b_fc,  // layer1: [1]
            float* __restrict__ out)
{
    ulonglong2* Wsm    = (ulonglong2*)dynsm;            // [32][256]
    float*      h_sm   = (float*)(dynsm + 32*256*16);   // [2][128]
    float*      gate_sm= h_sm + 2 * HID;                // [2][512]

    const int tid = threadIdx.x;
    const int b0  = blockIdx.x * 2;
    const int r0  = tid;
    const int r1  = 256 + tid;

    // ---- weight staging: row r0 -> smem (k-major), row r1 -> registers ----
    const ulonglong2* w0p = (const ulonglong2*)(W_hh + (size_t)r0 * HID);
    const ulonglong2* w1p = (const ulonglong2*)(W_hh + (size_t)r1 * HID);
    ulonglong2 wreg[32];
    #pragma unroll
    for (int j = 0; j < 32; j++) {
        Wsm[j * 256 + tid] = w0p[j];
        wreg[j] = w1p[j];
    }

    float wih0 = 0.f, wih1 = 0.f, bias0 = 0.f, bias1 = 0.f;
    if (LAYER == 0) {
        wih0  = __ldg(&W_ih[r0]);
        wih1  = __ldg(&W_ih[r1]);
        bias0 = __ldg(&b_ih[r0]) + __ldg(&b_hh[r0]);
        bias1 = __ldg(&b_ih[r1]) + __ldg(&b_hh[r1]);
    }

    h_sm[tid] = 0.f;           // tid covers [0, 2*HID)
    float c = 0.f;             // cell state: thread owns (ub, uj)
    __syncthreads();

    const ulonglong2* hp0 = (const ulonglong2*)h_sm;          // 32 chunks
    const ulonglong2* hp1 = (const ulonglong2*)(h_sm + HID);
    const int ub = tid >> 7;           // batch slot 0/1
    const int uj = tid & (HID - 1);    // hidden index

    for (int t = 0; t < TT; t++) {
        // --- input-gate contributions for (row, batch) pairs ---
        float xg00, xg01, xg10, xg11;
        if (LAYER == 0) {
            float xv0 = __ldg(&x[(size_t)b0 * TT + t]);
            float xv1 = __ldg(&x[(size_t)(b0 + 1) * TT + t]);
            xg00 = fmaf(wih0, xv0, bias0);
            xg01 = fmaf(wih0, xv1, bias0);
            xg10 = fmaf(wih1, xv0, bias1);
            xg11 = fmaf(wih1, xv1, bias1);
        } else {
            const float* p0 = g_xg1 + ((size_t)b0 * TT + t) * G4;
            const float* p1 = g_xg1 + ((size_t)(b0 + 1) * TT + t) * G4;
            xg00 = __ldg(p0 + r0);
            xg01 = __ldg(p1 + r0);
            xg10 = __ldg(p0 + r1);
            xg11 = __ldg(p1 + r1);
        }

        // --- 4 dots of length 128, K-packed f32x2, 2 chains each ---
        ull a00a = pk2(xg00, 0.f), a00b = pk2(0.f, 0.f);
        ull a01a = pk2(xg01, 0.f), a01b = pk2(0.f, 0.f);
        ull a10a = pk2(xg10, 0.f), a10b = pk2(0.f, 0.f);
        ull a11a = pk2(xg11, 0.f), a11b = pk2(0.f, 0.f);

        #pragma unroll
        for (int j = 0; j < 32; j++) {
            ulonglong2 wA = Wsm[j * 256 + tid];   // row r0 weights (smem)
            ulonglong2 h0 = hp0[j];               // broadcast
            ulonglong2 h1 = hp1[j];               // broadcast
            ulonglong2 wB = wreg[j];              // row r1 weights (regs)
            ffma2(a00a, wA.x, h0.x); ffma2(a00b, wA.y, h0.y);
            ffma2(a01a, wA.x, h1.x); ffma2(a01b, wA.y, h1.y);
            ffma2(a10a, wB.x, h0.x); ffma2(a10b, wB.y, h0.y);
            ffma2(a11a, wB.x, h1.x); ffma2(a11b, wB.y, h1.y);
        }

        float2 f;
        f = upk(a00a); float a00 = f.x + f.y; f = upk(a00b); a00 += f.x + f.y;
        f = upk(a01a); float a01 = f.x + f.y; f = upk(a01b); a01 += f.x + f.y;
        f = upk(a10a); float a10 = f.x + f.y; f = upk(a10b); a10 += f.x + f.y;
        f = upk(a11a); float a11 = f.x + f.y; f = upk(a11b); a11 += f.x + f.y;

        // --- activations: r0 is i (tid<128) or f -> sigmoid;
        //                  r1 is g (tid<128) -> tanh, else o -> sigmoid ---
        float g00 = sigm_f(a00);
        float g01 = sigm_f(a01);
        float g10, g11;
        if (tid < 128) { g10 = tanh_f(a10); g11 = tanh_f(a11); }
        else           { g10 = sigm_f(a10); g11 = sigm_f(a11); }

        gate_sm[r0]      = g00;
        gate_sm[G4 + r0] = g01;
        gate_sm[r1]      = g10;
        gate_sm[G4 + r1] = g11;
        __syncthreads();

        // --- cell/hidden update: all 256 threads, thread owns (ub, uj) ---
        {
            const float* gb = gate_sm + ub * G4;
            float iv = gb[uj];
            float fv = gb[HID + uj];
            float gv = gb[2 * HID + uj];
            float ov = gb[3 * HID + uj];
            c = fmaf(fv, c, iv * gv);
            float h = ov * tanh_f(c);
            h_sm[tid] = h;                         // tid == ub*HID + uj
            if (LAYER == 0)
                g_out0[((size_t)(b0 + ub) * TT + t) * HID + uj] = h;
        }
        __syncthreads();
    }

    // --- final h_n / c_n. out layout: y[256] | h_n[2][256][128] | c_n[2][256][128]
    {
        int bglob = b0 + ub;
        out[256 + ((size_t)LAYER * BATCH + bglob) * HID + uj] = h_sm[tid];
        out[256 + (size_t)2 * BATCH * HID
                + ((size_t)LAYER * BATCH + bglob) * HID + uj] = c;
    }

    // --- FC head (layer 1 only): y[b] = h_final[b] . W_fc + b_fc ---
    if (LAYER == 1 && tid < 64) {
        int w = tid >> 5;          // batch slot 0/1
        int l = tid & 31;
        float s = 0.f;
        #pragma unroll
        for (int j = l; j < HID; j += 32)
            s = fmaf(h_sm[w * HID + j], __ldg(&W_fc[j]), s);
        #pragma unroll
        for (int off = 16; off > 0; off >>= 1)
            s += __shfl_down_sync(0xffffffffu, s, off);
        if (l == 0)
            out[b0 + w] = s + __ldg(&b_fc[0]);
    }
}

// ---------------------------------------------------------------------------
// tf32 tensor-core GEMM: g_xg1[M,512] = g_out0[M,128] @ W_ih1^T + bias
// CTA 256 threads / 8 warps; tile 128m x 64n, K=128 single pass.
// mma.sync.m16n8k8 tf32. Warp w owns m rows [w*16, w*16+16), all 64 n.
// Operands staged in FRAGMENT-ORDER smem:
//   Asw[s][w][lane][4 regs]          (16B/lane -> conflict-free LDS.128)
//   Bsw[s][lane][16 regs (+4 pad)]   (80B stride -> all-32-bank, 4x LDS.128)
// Hot loop per k-step: 1 + 4 LDS.128 + 8 HMMA.
// ---------------------------------------------------------------------------
#define ASW_U (16*8*32*4)     // 16384 uints
#define BSW_U (16*32*20)      // 10240 uints
#define SMEM_GEMM ((ASW_U + BSW_U + 64) * 4)   // 106752 B

__global__ void __launch_bounds__(256, 2)
gemm_xg1_kernel(const float* __restrict__ W,     // W_ih_l1 [512,128]
                const float* __restrict__ b_ih,
                const float* __restrict__ b_hh)
{
    uint32_t* Asw    = (uint32_t*)dynsm;
    uint32_t* Bsw    = Asw + ASW_U;
    float*    bias_s = (float*)(Bsw + BSW_U);

    const int tid = threadIdx.x;
    const int n0  = blockIdx.x * 64;
    const int m0  = blockIdx.y * 128;

    if (tid < 64)
        bias_s[tid] = __ldg(&b_ih[n0 + tid]) + __ldg(&b_hh[n0 + tid]);

    // ---- stage A (128m x 128k): row-major global -> fragment order ----
    {
        const int row = tid >> 1;             // 0..127
        const int kh  = (tid & 1) * 64;       // k half
        const int w   = row >> 4;
        const int g   = row & 7;
        const int rb  = (row >> 3) & 1;       // row g vs g+8 within m16 tile
        const float4* ap = (const float4*)(g_out0 + (size_t)(m0 + row) * HID + kh);
        #pragma unroll
        for (int q = 0; q < 16; q++) {
            float4 v = ap[q];
            int k  = kh + q * 4;              // k%4 == 0 -> 4 elems span tig 0..3
            int s  = k >> 3;
            int kb = (k >> 2) & 1;            // col tig vs tig+4
            uint32_t* dst = &Asw[(((s * 8 + w) * 32) + g * 4) * 4 + (rb + kb * 2)];
            dst[0]  = cvt_tf32(v.x);
            dst[4]  = cvt_tf32(v.y);
            dst[8]  = cvt_tf32(v.z);
            dst[12] = cvt_tf32(v.w);
        }
    }
    // ---- stage B (64n x 128k): W rows n0..n0+63 -> fragment order ----
    {
        const int bn  = tid & 63;             // n row
        const int kh  = (tid >> 6) * 32;      // k segment of 32
        const int nt  = bn >> 3;
        const int gg  = bn & 7;
        const float4* bp = (const float4*)(W + (size_t)(n0 + bn) * HID + kh);
        #pragma unroll
        for (int q = 0; q < 8; q++) {
            float4 v = bp[q];
            int k  = kh + q * 4;
            int s  = k >> 3;
            int kb = (k >> 2) & 1;            // b0 vs b1
            uint32_t* dst = &Bsw[(s * 32 + gg * 4) * 20 + nt * 2 + kb];
            dst[0]  = cvt_tf32(v.x);
            dst[20] = cvt_tf32(v.y);
            dst[40] = cvt_tf32(v.z);
            dst[60] = cvt_tf32(v.w);
        }
    }
    __syncthreads();

    // ---- compute: warp w, lane l ----
    const int w = tid >> 5;
    const int l = tid & 31;

    float acc[8][4];
    #pragma unroll
    for (int i = 0; i < 8; i++)
        #pragma unroll
        for (int j = 0; j < 4; j++) acc[i][j] = 0.f;

    #pragma unroll
    for (int s = 0; s < 16; s++) {
        uint4 a = *(const uint4*)&Asw[((s * 8 + w) * 32 + l) * 4];
        const uint32_t* bb = &Bsw[(s * 32 + l) * 20];
        uint4 b0 = *(const uint4*)(bb + 0);   // nt0{r0,r1} nt1{r0,r1}
        uint4 b1 = *(const uint4*)(bb + 4);
        uint4 b2 = *(const uint4*)(bb + 8);
        uint4 b3 = *(const uint4*)(bb + 12);
        mma_tf32(acc[0], a, b0.x, b0.y); mma_tf32(acc[1], a, b0.z, b0.w);
        mma_tf32(acc[2], a, b1.x, b1.y); mma_tf32(acc[3], a, b1.z, b1.w);
        mma_tf32(acc[4], a, b2.x, b2.y); mma_tf32(acc[5], a, b2.z, b2.w);
        mma_tf32(acc[6], a, b3.x, b3.y); mma_tf32(acc[7], a, b3.z, b3.w);
    }

    // ---- epilogue: c0,c1 -> (row g, cols 2*tig, 2*tig+1); c2,c3 -> row g+8 ----
    const int g   = l >> 2;
    const int tig = l & 3;
    const size_t row0 = (size_t)(m0 + w * 16 + g);
    #pragma unroll
    for (int nt = 0; nt < 8; nt++) {
        int colb = nt * 8 + tig * 2;
        float bv0 = bias_s[colb], bv1 = bias_s[colb + 1];
        *(float2*)&g_xg1[row0 * G4 + n0 + colb] =
            make_float2(acc[nt][0] + bv0, acc[nt][1] + bv1);
        *(float2*)&g_xg1[(row0 + 8) * G4 + n0 + colb] =
            make_float2(acc[nt][2] + bv0, acc[nt][3] + bv1);
    }
}

// ---------------------------------------------------------------------------
// Launch
// ---------------------------------------------------------------------------
extern "C" void kernel_launch(void* const* d_in, const int* in_sizes, int n_in,
                              void* d_out, int out_size)
{
    const float* x      = (const float*)d_in[0];   // [256,2048,1]
    const float* W_ih0  = (const float*)d_in[1];   // [512,1]
    const float* W_hh0  = (const float*)d_in[2];   // [512,128]
    const float* b_ih0  = (const float*)d_in[3];
    const float* b_hh0  = (const float*)d_in[4];
    const float* W_ih1  = (const float*)d_in[5];   // [512,128]
    const float* W_hh1  = (const float*)d_in[6];   // [512,128]
    const float* b_ih1  = (const float*)d_in[7];
    const float* b_hh1  = (const float*)d_in[8];
    const float* W_fc   = (const float*)d_in[9];   // [1,128]
    const float* b_fc   = (const float*)d_in[10];  // [1]
    float* out = (float*)d_out;

    cudaFuncSetAttribute(lstm_kernel<0>, cudaFuncAttributeMaxDynamicSharedMemorySize, SMEM_LSTM);
    cudaFuncSetAttribute(lstm_kernel<1>, cudaFuncAttributeMaxDynamicSharedMemorySize, SMEM_LSTM);
    cudaFuncSetAttribute(gemm_xg1_kernel, cudaFuncAttributeMaxDynamicSharedMemorySize, SMEM_GEMM);

    // Layer 0 recurrence (writes g_out0, h_n[0], c_n[0])
    lstm_kernel<0><<<BATCH/2, 256, SMEM_LSTM>>>(
        x, W_ih0, W_hh0, b_ih0, b_hh0, nullptr, nullptr, out);

    // Layer 1 input gates: g_xg1 = g_out0 @ W_ih1^T + bias  (tf32 tensor cores)
    {
        dim3 grid(G4 / 64, MROWS / 128);   // x = n-tile fastest (A-tile L2 reuse)
        gemm_xg1_kernel<<<grid, 256, SMEM_GEMM>>>(W_ih1, b_ih1, b_hh1);
    }

    // Layer 1 recurrence (reads g_xg1; writes h_n[1], c_n[1], y)
    lstm_kernel<1><<<BATCH/2, 256, SMEM_LSTM>>>(
        nullptr, nullptr, W_hh1, b_ih1, b_hh1, W_fc, b_fc, out);
}